// round 10
// baseline (speedup 1.0000x reference)
#include <cuda_runtime.h>

#define H    16
#define NBOX 128
#define DIN  256
#define DKD  128
#define DG   64

typedef unsigned long long ull;

// Scratch (device globals — no allocations allowed)
__device__ float g_glog[H * NBOX * NBOX];      // log(clip(relu(gate))): 1 MB
__device__ float g_qkv[3 * H * NBOX * DKD];    // k,q,v projections: 3 MB
__device__ float g_partial[H * 4 * DKD];       // per-mtile partial colsums

// ---- packed f32x2 helpers (sm_10x FFMA2) ----------------------------------
__device__ __forceinline__ void fma2(ull& acc, ull a, ull b) {
    asm("fma.rn.f32x2 %0, %1, %2, %0;" : "+l"(acc) : "l"(a), "l"(b));
}
__device__ __forceinline__ ull dup2(float a) {
    ull r; asm("mov.b64 %0, {%1, %1};" : "=l"(r) : "f"(a)); return r;
}
__device__ __forceinline__ float2 unpack2(ull v) {
    float2 r; asm("mov.b64 {%0, %1}, %2;" : "=f"(r.x), "=f"(r.y) : "l"(v)); return r;
}

// Dynamic smem layout (proj):
//   AsR: 128 x 257 f32  = 131584 B  (pad 257 -> lane L reading row L+32i is
//                                    conflict-free: bank = (L + d) mod 32)
//   Ws2: 256 x 34 ull   =  69632 B  (row stride 272 B = 16-aligned; 64 cols
//                                    as 32 f32x2 pairs + 2 pad)
#define DS_A_PAD   257
#define DS_W_PAD   34
#define DS_TOTAL   (128 * DS_A_PAD * 4 + 256 * DS_W_PAD * 8)   // 201216

// ---------------------------------------------------------------------------
// k_front (256 threads, 352 blocks, ~201 KB dynamic smem, 1 block/SM):
//   blocks [0,96): proj: C(128 x 64) = f_a(128x256) @ W[h,p][:, c0..c0+64) + b
//     * A + W half-panel staged ONCE; ONE __syncthreads; 256-d loop has no
//       barriers and no global loads.
//     * warp = 128 rows x 8 cols; thread = rows {L,L+32,L+64,L+96} x 8 cols.
//       Per warp-d: 4 conflict-free LDS.32 (A) + 2 uniform LDS.128 (W) = 6 wf
//       vs 16 FFMA2 = 32 FMA-cyc -> crossbar at 75%, FMA-bound.
//   blocks [96,352): gate: glog[h,m,n] = log(max(pos[m,n,:]·WG[h]+bg[h],1e-6))
// ---------------------------------------------------------------------------
__global__ void __launch_bounds__(256) k_front(
        const float* __restrict__ f_a,
        const float* __restrict__ pos,
        const float* __restrict__ WG, const float* __restrict__ bg,
        const float* __restrict__ WK, const float* __restrict__ bk,
        const float* __restrict__ WQ, const float* __restrict__ bq,
        const float* __restrict__ WV, const float* __restrict__ bv) {
    extern __shared__ __align__(16) char dsm[];
    int tid = threadIdx.x;

    if (blockIdx.x < 96) {
        // ---------------- proj path ----------------
        float (*AsR)[DS_A_PAD] = (float(*)[DS_A_PAD])dsm;
        ull   (*Ws2)[DS_W_PAD] = (ull(*)[DS_W_PAD])(dsm + 128 * DS_A_PAD * 4);

        int bid = blockIdx.x;
        int ct = bid & 1;               // col half: cols 64ct .. 64ct+63
        int p  = (bid >> 1) % 3;
        int h  = bid / 6;
        const float* W  = (p == 0) ? WK : ((p == 1) ? WQ : WV);
        const float* bb = (p == 0) ? bk : ((p == 1) ? bq : bv);
        const float* Wh = W + (long)h * DIN * DKD;
        int c0 = 64 * ct;

        int w = tid >> 5, L = tid & 31;
        int cp0 = 4 * w;                // warp col-pairs 4w..4w+3 (local cols 8w..8w+7)

        // ---- stage A: 128x256, coalesced LDG.128, scalar STS ----
#pragma unroll
        for (int it = 0; it < 32; ++it) {
            int fidx = tid + 256 * it;          // 0..8191
            int r = fidx >> 6, c4 = fidx & 63;
            float4 v = *(const float4*)&f_a[r * DIN + 4 * c4];
            AsR[r][4 * c4 + 0] = v.x;
            AsR[r][4 * c4 + 1] = v.y;
            AsR[r][4 * c4 + 2] = v.z;
            AsR[r][4 * c4 + 3] = v.w;
        }
        // ---- stage W half-panel: 256 x 64 as f32x2 col-pairs ----
#pragma unroll
        for (int it = 0; it < 16; ++it) {
            int fidx = tid + 256 * it;          // 0..4095
            int d = fidx >> 4, q = fidx & 15;   // floats [4q, 4q+4) of row d
            ulonglong2 v = *(const ulonglong2*)&Wh[d * DKD + c0 + 4 * q];
            *(ulonglong2*)&Ws2[d][2 * q] = v;
        }
        __syncthreads();   // the ONLY barrier

        ull acc[4][4] = {};   // [row i (L+32i)][col-pair]

        // software-pipelined 256-d loop: zero barriers, zero global loads
        float a0 = AsR[L +  0][0];
        float a1 = AsR[L + 32][0];
        float a2 = AsR[L + 64][0];
        float a3 = AsR[L + 96][0];
        ulonglong2 w0 = *(ulonglong2*)&Ws2[0][cp0 + 0];
        ulonglong2 w1 = *(ulonglong2*)&Ws2[0][cp0 + 2];

#pragma unroll 4
        for (int d = 0; d < DIN - 1; ++d) {
            float n0 = AsR[L +  0][d + 1];
            float n1 = AsR[L + 32][d + 1];
            float n2 = AsR[L + 64][d + 1];
            float n3 = AsR[L + 96][d + 1];
            ulonglong2 m0 = *(ulonglong2*)&Ws2[d + 1][cp0 + 0];
            ulonglong2 m1 = *(ulonglong2*)&Ws2[d + 1][cp0 + 2];
            ull A0 = dup2(a0), A1 = dup2(a1), A2 = dup2(a2), A3 = dup2(a3);
            fma2(acc[0][0], A0, w0.x);  fma2(acc[0][1], A0, w0.y);
            fma2(acc[0][2], A0, w1.x);  fma2(acc[0][3], A0, w1.y);
            fma2(acc[1][0], A1, w0.x);  fma2(acc[1][1], A1, w0.y);
            fma2(acc[1][2], A1, w1.x);  fma2(acc[1][3], A1, w1.y);
            fma2(acc[2][0], A2, w0.x);  fma2(acc[2][1], A2, w0.y);
            fma2(acc[2][2], A2, w1.x);  fma2(acc[2][3], A2, w1.y);
            fma2(acc[3][0], A3, w0.x);  fma2(acc[3][1], A3, w0.y);
            fma2(acc[3][2], A3, w1.x);  fma2(acc[3][3], A3, w1.y);
            a0 = n0; a1 = n1; a2 = n2; a3 = n3; w0 = m0; w1 = m1;
        }
        {   // last d
            ull A0 = dup2(a0), A1 = dup2(a1), A2 = dup2(a2), A3 = dup2(a3);
            fma2(acc[0][0], A0, w0.x);  fma2(acc[0][1], A0, w0.y);
            fma2(acc[0][2], A0, w1.x);  fma2(acc[0][3], A0, w1.y);
            fma2(acc[1][0], A1, w0.x);  fma2(acc[1][1], A1, w0.y);
            fma2(acc[1][2], A1, w1.x);  fma2(acc[1][3], A1, w1.y);
            fma2(acc[2][0], A2, w0.x);  fma2(acc[2][1], A2, w0.y);
            fma2(acc[2][2], A2, w1.x);  fma2(acc[2][3], A2, w1.y);
            fma2(acc[3][0], A3, w0.x);  fma2(acc[3][1], A3, w0.y);
            fma2(acc[3][2], A3, w1.x);  fma2(acc[3][3], A3, w1.y);
        }

        // epilogue: rows L+32i, cols c0+8w .. c0+8w+7
        float* outp = g_qkv + (long)(p * H + h) * NBOX * DKD;
        int colg = c0 + 8 * w;
        float4 bLo = *(const float4*)&bb[h * DKD + colg];
        float4 bHi = *(const float4*)&bb[h * DKD + colg + 4];
#pragma unroll
        for (int i = 0; i < 4; ++i) {
            int row = L + 32 * i;
            float2 u0 = unpack2(acc[i][0]);
            float2 u1 = unpack2(acc[i][1]);
            float2 u2 = unpack2(acc[i][2]);
            float2 u3 = unpack2(acc[i][3]);
            *(float4*)&outp[row * DKD + colg] =
                make_float4(u0.x + bLo.x, u0.y + bLo.y, u1.x + bLo.z, u1.y + bLo.w);
            *(float4*)&outp[row * DKD + colg + 4] =
                make_float4(u2.x + bHi.x, u2.y + bHi.y, u3.x + bHi.z, u3.y + bHi.w);
        }
    } else {
        // ---------------- gate path ----------------
        float (*pos_s)[65] = (float(*)[65])dsm;              // 64x65 = 16640 B
        float* wg_s = (float*)(dsm + 64 * 65 * 4);           // 16x64 =  4096 B

        int p0 = (blockIdx.x - 96) * 64;   // pair base (pair = m*128+n)

        ((float4*)wg_s)[tid] = ((const float4*)WG)[tid];
#pragma unroll
        for (int it = 0; it < 4; ++it) {
            int fidx = tid + 256 * it;
            int pl = fidx >> 4, g4 = fidx & 15;
            float4 v = ((const float4*)pos)[(long)(p0 + pl) * 16 + g4];
            pos_s[pl][4 * g4 + 0] = v.x;
            pos_s[pl][4 * g4 + 1] = v.y;
            pos_s[pl][4 * g4 + 2] = v.z;
            pos_s[pl][4 * g4 + 3] = v.w;
        }
        __syncthreads();

        int row = tid & 63;
        int hg  = tid >> 6;       // heads {hg, hg+4, hg+8, hg+12}
        float acc[4] = {0.f, 0.f, 0.f, 0.f};
#pragma unroll
        for (int g = 0; g < DG; ++g) {
            float pv = pos_s[row][g];
#pragma unroll
            for (int j = 0; j < 4; ++j)
                acc[j] = fmaf(pv, wg_s[(hg + 4 * j) * DG + g], acc[j]);
        }
#pragma unroll
        for (int j = 0; j < 4; ++j) {
            int h = hg + 4 * j;
            float x = acc[j] + bg[h];
            g_glog[h * (NBOX * NBOX) + p0 + row] = __logf(fmaxf(x, 1e-6f));
        }
    }
}

// ---------------------------------------------------------------------------
// k_attn: 32x128 score tile (f32x2 FMA), + glog, row softmax, partial colsums.
// grid (4, 16), 256 threads.
// ---------------------------------------------------------------------------
__global__ void k_attn() {
    __shared__ __align__(16) ull As2[32][33];
    __shared__ __align__(16) float Bs[32][132];
    __shared__ float psum[8][128];

    int tid = threadIdx.x;
    int mt = blockIdx.x, h = blockIdx.y;
    int m0 = mt * 32;
    int rg = tid >> 5;
    int cg = tid & 31;

    const float* kmat = g_qkv + (long)(0 * H + h) * NBOX * DKD;
    const float* qmat = g_qkv + (long)(1 * H + h) * NBOX * DKD;

    ull acc[4][2] = {};

    for (int kk = 0; kk < DKD; kk += 32) {
        {
            int r = tid >> 3, c4 = tid & 7;
            float4 v = *(const float4*)&kmat[(m0 + r) * DKD + kk + 4 * c4];
            As2[r][4 * c4 + 0] = dup2(v.x);
            As2[r][4 * c4 + 1] = dup2(v.y);
            As2[r][4 * c4 + 2] = dup2(v.z);
            As2[r][4 * c4 + 3] = dup2(v.w);
        }
#pragma unroll
        for (int it = 0; it < 4; ++it) {
            int fidx = tid + 256 * it;
            int n = fidx >> 3, c4 = fidx & 7;
            float4 v = *(const float4*)&qmat[n * DKD + kk + 4 * c4];
            Bs[4 * c4 + 0][n] = v.x;
            Bs[4 * c4 + 1][n] = v.y;
            Bs[4 * c4 + 2][n] = v.z;
            Bs[4 * c4 + 3][n] = v.w;
        }
        __syncthreads();

#pragma unroll
        for (int d = 0; d < 32; ++d) {
            ulonglong2 b = *(ulonglong2*)&Bs[d][4 * cg];
#pragma unroll
            for (int i = 0; i < 4; ++i) {
                ull a = As2[4 * rg + i][d];
                fma2(acc[i][0], a, b.x);
                fma2(acc[i][1], a, b.y);
            }
        }
        __syncthreads();
    }

    const float scale = 0.08838834764831843f;  // 1/sqrt(128)
    float csum[4] = {0.f, 0.f, 0.f, 0.f};
#pragma unroll
    for (int i = 0; i < 4; ++i) {
        int m = m0 + 4 * rg + i;
        float4 gl = *(const float4*)&g_glog[((long)h * NBOX + m) * NBOX + 4 * cg];
        float2 s0 = unpack2(acc[i][0]);
        float2 s1 = unpack2(acc[i][1]);
        float l[4];
        l[0] = s0.x * scale + gl.x;
        l[1] = s0.y * scale + gl.y;
        l[2] = s1.x * scale + gl.z;
        l[3] = s1.y * scale + gl.w;

        float mx = fmaxf(fmaxf(l[0], l[1]), fmaxf(l[2], l[3]));
#pragma unroll
        for (int off = 16; off; off >>= 1)
            mx = fmaxf(mx, __shfl_xor_sync(0xffffffffu, mx, off));

        float e[4], s = 0.f;
#pragma unroll
        for (int j = 0; j < 4; ++j) { e[j] = __expf(l[j] - mx); s += e[j]; }
#pragma unroll
        for (int off = 16; off; off >>= 1)
            s += __shfl_xor_sync(0xffffffffu, s, off);

        float rinv = 1.0f / s;
#pragma unroll
        for (int j = 0; j < 4; ++j) csum[j] += e[j] * rinv;
    }

#pragma unroll
    for (int j = 0; j < 4; ++j) psum[rg][4 * cg + j] = csum[j];
    __syncthreads();

    if (tid < 128) {
        float s = 0.f;
#pragma unroll
        for (int ww = 0; ww < 8; ++ww) s += psum[ww][tid];
        g_partial[(h * 4 + mt) * DKD + tid] = s;
    }
}

// ---------------------------------------------------------------------------
// k_out: out[i, c, d] = v[h,i,k]*colsum[h,k] + f_a[i,d]   (c = h*128+k)
// colsum computed inline from 4 partials. 16.7M float4 streaming stores.
// ---------------------------------------------------------------------------
__global__ void k_out(const float* __restrict__ f_a, float4* __restrict__ out) {
    int idx = blockIdx.x * 512 + threadIdx.x;   // 0..2^24-1
    int d4 = idx & 63;
    int c  = (idx >> 6) & 2047;
    int i  = idx >> 17;
    int h  = c >> 7;
    int k  = c & 127;

    float cs = g_partial[(h * 4 + 0) * DKD + k]
             + g_partial[(h * 4 + 1) * DKD + k]
             + g_partial[(h * 4 + 2) * DKD + k]
             + g_partial[(h * 4 + 3) * DKD + k];
    float s = g_qkv[((long)(2 * H + h) * NBOX + i) * DKD + k] * cs;
    float4 f = ((const float4*)f_a)[i * 64 + d4];
    __stcs(&out[idx], make_float4(s + f.x, s + f.y, s + f.z, s + f.w));
}

// ---------------------------------------------------------------------------
extern "C" void kernel_launch(void* const* d_in, const int* in_sizes, int n_in,
                              void* d_out, int out_size) {
    const float* f_a = (const float*)d_in[0];
    const float* pos = (const float*)d_in[1];
    const float* WG  = (const float*)d_in[2];
    const float* bg  = (const float*)d_in[3];
    const float* WK  = (const float*)d_in[4];
    const float* bk  = (const float*)d_in[5];
    const float* WQ  = (const float*)d_in[6];
    const float* bq  = (const float*)d_in[7];
    const float* WV  = (const float*)d_in[8];
    const float* bv  = (const float*)d_in[9];

    cudaFuncSetAttribute(k_front, cudaFuncAttributeMaxDynamicSharedMemorySize,
                         DS_TOTAL);

    k_front<<<352, 256, DS_TOTAL>>>(f_a, pos, WG, bg, WK, bk, WQ, bq, WV, bv);
    k_attn<<<dim3(4, 16), 256>>>();
    k_out<<<32768, 512>>>(f_a, (float4*)d_out);
}